// round 16
// baseline (speedup 1.0000x reference)
#include <cuda_runtime.h>
#include <cuda_fp16.h>
#include <math.h>
#include <stdint.h>

// Problem constants
#define B_  2
#define T_  2048
#define D_  2048
#define H_  16
#define HD_ 128

// ---------------- scratch (static device globals; no allocation) -------------
__device__ __align__(16) __half g_q[(size_t)B_ * H_ * T_ * HD_];   // rope applied
__device__ __align__(16) __half g_k[(size_t)B_ * H_ * T_ * HD_];
__device__ __align__(16) __half g_v[(size_t)B_ * H_ * T_ * HD_];
__device__ __align__(16) __half g_y[(size_t)B_ * T_ * D_];         // attn output
__device__ __align__(16) __half g_xh[(size_t)B_ * T_ * D_];        // x fp16
__device__ __align__(16) __half g_wqh[(size_t)D_ * 3 * HD_ * H_];  // w_qkv fp16
__device__ __align__(16) __half g_woh[(size_t)D_ * D_];            // w_out fp16
__device__ float2 g_rope_tab[T_ * 64];                             // (cos, sin)

// element counts (float4 granules)
#define NX4  (B_ * T_ * D_ / 4)
#define NWQ4 (D_ * 3 * HD_ * H_ / 4)
#define NWO4 (D_ * D_ / 4)

// ============================================================================
// helpers
// ============================================================================
__device__ __forceinline__ uint32_t h2_u32(__half2 h) {
    return *reinterpret_cast<uint32_t*>(&h);
}

__device__ __forceinline__ void mma_f16(float c[4],
                                        uint32_t a0, uint32_t a1, uint32_t a2, uint32_t a3,
                                        uint32_t b0, uint32_t b1) {
    asm volatile(
        "mma.sync.aligned.m16n8k16.row.col.f32.f16.f16.f32 "
        "{%0,%1,%2,%3}, {%4,%5,%6,%7}, {%8,%9}, {%0,%1,%2,%3};"
        : "+f"(c[0]), "+f"(c[1]), "+f"(c[2]), "+f"(c[3])
        : "r"(a0), "r"(a1), "r"(a2), "r"(a3), "r"(b0), "r"(b1));
}

__device__ __forceinline__ void ldsm_x4(uint32_t r[4], uint32_t addr) {
    asm volatile("ldmatrix.sync.aligned.m8n8.x4.shared.b16 {%0,%1,%2,%3}, [%4];"
                 : "=r"(r[0]), "=r"(r[1]), "=r"(r[2]), "=r"(r[3]) : "r"(addr));
}
__device__ __forceinline__ void ldsm_x4_t(uint32_t r[4], uint32_t addr) {
    asm volatile("ldmatrix.sync.aligned.m8n8.x4.trans.shared.b16 {%0,%1,%2,%3}, [%4];"
                 : "=r"(r[0]), "=r"(r[1]), "=r"(r[2]), "=r"(r[3]) : "r"(addr));
}

__device__ __forceinline__ void cpa16s(uint32_t saddr, const void* src) {
    asm volatile("cp.async.cg.shared.global [%0], [%1], 16;" :: "r"(saddr), "l"(src));
}
__device__ __forceinline__ void cpa_commit() { asm volatile("cp.async.commit_group;"); }
template<int N> __device__ __forceinline__ void cpa_wait() {
    asm volatile("cp.async.wait_group %0;" :: "n"(N));
}

__device__ __forceinline__ uint32_t smem_u32(const void* p) {
    uint32_t a;
    asm("{ .reg .u64 t; cvta.to.shared.u64 t, %1; cvt.u32.u64 %0, t; }" : "=r"(a) : "l"(p));
    return a;
}

// ============================================================================
// prep kernels
// ============================================================================
__global__ void rope_tab_kernel()
{
    int idx = blockIdx.x * blockDim.x + threadIdx.x;
    if (idx >= T_ * 64) return;
    int t = idx >> 6, i = idx & 63;
    float inv = powf(10000.0f, -((float)(2 * i)) * (1.0f / 128.0f));
    float ang = (float)t * inv;
    float s, c;
    sincosf(ang, &s, &c);
    g_rope_tab[idx] = make_float2(c, s);
}

__device__ __forceinline__ uint2 f4_to_h4(float4 v) {
    return make_uint2(h2_u32(__floats2half2_rn(v.x, v.y)),
                      h2_u32(__floats2half2_rn(v.z, v.w)));
}

__global__ void conv_all_kernel(const float4* __restrict__ x,
                                const float4* __restrict__ wq,
                                const float4* __restrict__ wo)
{
    int i = blockIdx.x * blockDim.x + threadIdx.x;
    if (i < NX4) {
        ((uint2*)g_xh)[i] = f4_to_h4(x[i]);
        return;
    }
    i -= NX4;
    if (i < NWQ4) {
        ((uint2*)g_wqh)[i] = f4_to_h4(wq[i]);
        return;
    }
    i -= NWQ4;
    if (i < NWO4) {
        ((uint2*)g_woh)[i] = f4_to_h4(wo[i]);
    }
}

// ============================================================================
// fp16 GEMM 128x128, k-chunk 64, 256 threads (8 warps 2m x 4n), occ 2.
// 3-stage cp.async pipeline, one __syncthreads per k-chunk. (round-13 body)
// ============================================================================
#define AROW 72
#define BROW 136
#define ABUF_BYTES (128 * AROW * 2)                 // 18432
#define BBUF_BYTES (64 * BROW * 2)                  // 17408
#define STAGE_BYTES (ABUF_BYTES + BBUF_BYTES)       // 35840
#define GEMM_SMEM_BYTES (3 * STAGE_BYTES)           // 107520

struct GemmCtx { int m0, n0, lane, warp_m, warp_n; };

template <typename Epi>
__device__ __forceinline__ void gemm_f16_cpa(const __half* __restrict__ A,
                                             const __half* __restrict__ Bg,
                                             int Kd, int Nd, Epi epi)
{
    extern __shared__ __half smg[];
    const uint32_t sb = smem_u32(smg);

    const int tid = threadIdx.x;
    const int lane = tid & 31;
    const int warp = tid >> 5;
    const int warp_m = warp & 1;
    const int warp_n = warp >> 1;
    const int m0 = blockIdx.y * 128;
    const int n0 = blockIdx.x * 128;

    float acc[4][4][4];
#pragma unroll
    for (int mt = 0; mt < 4; mt++)
#pragma unroll
        for (int nt = 0; nt < 4; nt++)
#pragma unroll
            for (int e = 0; e < 4; e++) acc[mt][nt][e] = 0.f;

    const uint32_t a_off =
        (uint32_t)((warp_m * 64 + (lane & 7) + ((lane >> 3) & 1) * 8) * AROW +
                   (lane >> 4) * 8) * 2;
    const uint32_t b_off = (uint32_t)ABUF_BYTES +
        (uint32_t)(((lane & 7) + ((lane >> 3) & 1) * 8) * BROW +
                   warp_n * 32 + (lane >> 4) * 8) * 2;

#define LOADG(it, stage)                                                          \
    {                                                                             \
        uint32_t ab = sb + (stage) * STAGE_BYTES;                                 \
        uint32_t bb = ab + ABUF_BYTES;                                            \
        int kk = (it) * 64;                                                       \
        _Pragma("unroll")                                                         \
        for (int i = 0; i < 4; i++) {                                             \
            int idx = tid + 256 * i;                                              \
            int row = idx >> 3, c = idx & 7;                                      \
            cpa16s(ab + (uint32_t)(row * (AROW * 2) + c * 16),                    \
                   A + (size_t)(m0 + row) * Kd + kk + c * 8);                     \
        }                                                                         \
        _Pragma("unroll")                                                         \
        for (int i = 0; i < 4; i++) {                                             \
            int idx = tid + 256 * i;                                              \
            int row = idx >> 4, c = idx & 15;                                     \
            cpa16s(bb + (uint32_t)(row * (BROW * 2) + c * 16),                    \
                   Bg + (size_t)(kk + row) * Nd + n0 + c * 8);                    \
        }                                                                         \
        cpa_commit();                                                             \
    }

    const int nt = Kd / 64;   // 32
    LOADG(0, 0);
    LOADG(1, 1);

    for (int it = 0; it < nt; it++) {
        if (it + 1 < nt) cpa_wait<1>(); else cpa_wait<0>();
        __syncthreads();

        if (it + 2 < nt) LOADG(it + 2, (it + 2) % 3);

        const uint32_t base = sb + (it % 3) * STAGE_BYTES;
#pragma unroll
        for (int s = 0; s < 4; s++) {
            uint32_t af[4][4];
#pragma unroll
            for (int mt = 0; mt < 4; mt++)
                ldsm_x4(af[mt], base + a_off + (uint32_t)(mt * 16 * AROW * 2 + s * 32));
            uint32_t bf[2][4];
#pragma unroll
            for (int nt2 = 0; nt2 < 2; nt2++)
                ldsm_x4_t(bf[nt2], base + b_off + (uint32_t)(s * 16 * BROW * 2 + nt2 * 32));
#pragma unroll
            for (int mt = 0; mt < 4; mt++)
#pragma unroll
                for (int ntv = 0; ntv < 4; ntv++)
                    mma_f16(acc[mt][ntv],
                            af[mt][0], af[mt][1], af[mt][2], af[mt][3],
                            bf[ntv >> 1][(ntv & 1) * 2], bf[ntv >> 1][(ntv & 1) * 2 + 1]);
        }
    }
#undef LOADG

    GemmCtx ctx{m0, n0, lane, warp_m, warp_n};
    epi(ctx, acc);
}

// ---------------- epilogues --------------------------------------------------
__device__ __forceinline__ void qkv_scatter_pair(int row, int col, float v0, float v1)
{
    int b = row >> 11, t = row & (T_ - 1);
    int h = col / (3 * HD_);
    int r = col % (3 * HD_);                 // always even
    size_t base = (((size_t)(b * H_ + h)) * T_ + t) * HD_;
    if (r < 2 * HD_) {
        __half* dst = (r < HD_) ? g_q : g_k;
        int rr = r & (HD_ - 1);
        float2 cs = g_rope_tab[(t << 6) + (rr >> 1)];
        float o0 = v0 * cs.x - v1 * cs.y;
        float o1 = v0 * cs.y + v1 * cs.x;
        *(__half2*)&dst[base + rr] = __floats2half2_rn(o0, o1);
    } else {
        *(__half2*)&g_v[base + r - 2 * HD_] = __floats2half2_rn(v0, v1);
    }
}

struct QkvEpi {
    __device__ __forceinline__ void operator()(const GemmCtx& c, float acc[4][4][4]) const {
#pragma unroll
        for (int mt = 0; mt < 4; mt++) {
            int row = c.m0 + c.warp_m * 64 + mt * 16 + (c.lane >> 2);
#pragma unroll
            for (int nt = 0; nt < 4; nt++) {
                int col = c.n0 + c.warp_n * 32 + nt * 8 + (c.lane & 3) * 2;
                qkv_scatter_pair(row,     col, acc[mt][nt][0], acc[mt][nt][1]);
                qkv_scatter_pair(row + 8, col, acc[mt][nt][2], acc[mt][nt][3]);
            }
        }
    }
};

struct OutEpi {
    float* C;
    __device__ __forceinline__ void operator()(const GemmCtx& c, float acc[4][4][4]) const {
#pragma unroll
        for (int mt = 0; mt < 4; mt++) {
            int row = c.m0 + c.warp_m * 64 + mt * 16 + (c.lane >> 2);
#pragma unroll
            for (int nt = 0; nt < 4; nt++) {
                int col = c.n0 + c.warp_n * 32 + nt * 8 + (c.lane & 3) * 2;
                *(float2*)(C + (size_t)row * D_ + col) =
                    make_float2(acc[mt][nt][0], acc[mt][nt][1]);
                *(float2*)(C + (size_t)(row + 8) * D_ + col) =
                    make_float2(acc[mt][nt][2], acc[mt][nt][3]);
            }
        }
    }
};

__global__ __launch_bounds__(256, 2) void gemm_qkv_kernel()
{
    gemm_f16_cpa(g_xh, g_wqh, D_, 3 * HD_ * H_, QkvEpi{});
}

__global__ __launch_bounds__(256, 2) void gemm_out_kernel(float* __restrict__ C)
{
    gemm_f16_cpa(g_y, g_woh, D_, D_, OutEpi{C});
}

// ============================================================================
// Flash attention, fp16 mma.m16n8k16, split-HD warp pairing:
// 512 threads = 16 warps. Warp pair p (warps 2p, 2p+1) owns q-rows
// [q0+16p, q0+16p+16). Each warp computes S + softmax redundantly
// (bit-identical) and PV for its half of HD (64 cols). ~96 live regs.
// ============================================================================
#define KROWH 136
#define KV_TILE_BYTES (64 * KROWH * 2)          // 17408
#define ATTN_SMEM_BYTES (4 * KV_TILE_BYTES)     // 69632
#define ATHREADS 512

__device__ __forceinline__ void load_kv(uint32_t sm_u, int buf,
                                        const __half* Kh, const __half* Vh,
                                        int k0, int tid)
{
    uint32_t kb = sm_u + buf * KV_TILE_BYTES;
    uint32_t vb = sm_u + 2 * KV_TILE_BYTES + buf * KV_TILE_BYTES;
#pragma unroll
    for (int i = 0; i < 2; i++) {
        int idx = tid + i * ATHREADS;
        int row = idx >> 4, c16 = idx & 15;
        cpa16s(kb + row * (KROWH * 2) + c16 * 16,
               Kh + (size_t)(k0 + row) * HD_ + c16 * 8);
    }
#pragma unroll
    for (int i = 0; i < 2; i++) {
        int idx = tid + i * ATHREADS;
        int row = idx >> 4, c16 = idx & 15;
        cpa16s(vb + row * (KROWH * 2) + c16 * 16,
               Vh + (size_t)(k0 + row) * HD_ + c16 * 8);
    }
    cpa_commit();
}

__global__ __launch_bounds__(ATHREADS, 1) void attn_kernel()
{
    extern __shared__ __half smh[];
    const uint32_t sm_u = smem_u32(smh);

    const int b = blockIdx.z, h = blockIdx.y;
    const int q0 = ((int)gridDim.x - 1 - (int)blockIdx.x) * 128;  // longest first
    const __half* Qh = g_q + (((size_t)(b * H_ + h)) * T_) * HD_;
    const __half* Kh = g_k + (((size_t)(b * H_ + h)) * T_) * HD_;
    const __half* Vh = g_v + (((size_t)(b * H_ + h)) * T_) * HD_;

    const int tid = threadIdx.x;
    const int lane = tid & 31;
    const int warp = tid >> 5;
    const int wpair = warp >> 1;       // 0..7 -> q-rows
    const int half = warp & 1;         // 0/1  -> HD half for PV
    const int r1 = lane >> 2;
    const int cc = lane & 3;
    const int qrow1 = q0 + wpair * 16 + r1;
    const int qrow2 = qrow1 + 8;
    const int ntile = (q0 >> 6) + 2;

    load_kv(sm_u, 0, Kh, Vh, 0, tid);

    uint32_t qf[8][4];
#pragma unroll
    for (int s = 0; s < 8; s++) {
        qf[s][0] = *(const uint32_t*)(Qh + (size_t)qrow1 * HD_ + 16 * s + 2 * cc);
        qf[s][1] = *(const uint32_t*)(Qh + (size_t)qrow2 * HD_ + 16 * s + 2 * cc);
        qf[s][2] = *(const uint32_t*)(Qh + (size_t)qrow1 * HD_ + 16 * s + 8 + 2 * cc);
        qf[s][3] = *(const uint32_t*)(Qh + (size_t)qrow2 * HD_ + 16 * s + 8 + 2 * cc);
    }

    float oacc[8][4];        // half of HD: 8 n-tiles of 8 cols
#pragma unroll
    for (int n = 0; n < 8; n++)
#pragma unroll
        for (int e = 0; e < 4; e++) oacc[n][e] = 0.f;
    float m1 = -1e30f, m2 = -1e30f, l1 = 0.f, l2 = 0.f;
    const float sm_scale = 0.08838834764831845f;

    const uint32_t k_off =
        (uint32_t)(((lane & 7) + (lane >> 4) * 8) * KROWH + ((lane >> 3) & 1) * 8) * 2;
    // V trans base shifted by this warp's HD half (64 cols = 128 bytes)
    const uint32_t v_off =
        (uint32_t)(((lane & 7) + ((lane >> 3) & 1) * 8) * KROWH + (lane >> 4) * 8) * 2 +
        (uint32_t)(half * 64 * 2);

    for (int t = 0; t < ntile; t++) {
        const int k0 = t * 64;
        const uint32_t Kb = sm_u + (t & 1) * KV_TILE_BYTES;
        const uint32_t Vb = sm_u + 2 * KV_TILE_BYTES + (t & 1) * KV_TILE_BYTES;

        if (t + 1 < ntile) {
            load_kv(sm_u, (t + 1) & 1, Kh, Vh, k0 + 64, tid);
            cpa_wait<1>();
        } else {
            cpa_wait<0>();
        }
        __syncthreads();

        // ---- S = Q K^T (full BN=64, duplicated across the warp pair) ----
        float sacc[8][4];
#pragma unroll
        for (int n = 0; n < 8; n++)
#pragma unroll
            for (int e = 0; e < 4; e++) sacc[n][e] = 0.f;

#pragma unroll
        for (int s = 0; s < 8; s++) {
#pragma unroll
            for (int j = 0; j < 4; j++) {
                uint32_t bb[4];
                ldsm_x4(bb, Kb + k_off + (uint32_t)(j * 16 * KROWH * 2 + s * 32));
                mma_f16(sacc[2 * j],     qf[s][0], qf[s][1], qf[s][2], qf[s][3], bb[0], bb[1]);
                mma_f16(sacc[2 * j + 1], qf[s][0], qf[s][1], qf[s][2], qf[s][3], bb[2], bb[3]);
            }
        }

        const bool need_mask = (t >= ntile - 2);
        float mx1 = -1e30f, mx2 = -1e30f;
#pragma unroll
        for (int n = 0; n < 8; n++) {
            int col = k0 + 8 * n + 2 * cc;
            float s0 = sacc[n][0] * sm_scale;
            float s1 = sacc[n][1] * sm_scale;
            float s2 = sacc[n][2] * sm_scale;
            float s3 = sacc[n][3] * sm_scale;
            if (need_mask) {
                if (col     > qrow1) s0 = -1e30f;
                if (col + 1 > qrow1) s1 = -1e30f;
                if (col     > qrow2) s2 = -1e30f;
                if (col + 1 > qrow2) s3 = -1e30f;
            }
            sacc[n][0] = s0; sacc[n][1] = s1; sacc[n][2] = s2; sacc[n][3] = s3;
            mx1 = fmaxf(mx1, fmaxf(s0, s1));
            mx2 = fmaxf(mx2, fmaxf(s2, s3));
        }
        mx1 = fmaxf(mx1, __shfl_xor_sync(0xffffffffu, mx1, 1));
        mx1 = fmaxf(mx1, __shfl_xor_sync(0xffffffffu, mx1, 2));
        mx2 = fmaxf(mx2, __shfl_xor_sync(0xffffffffu, mx2, 1));
        mx2 = fmaxf(mx2, __shfl_xor_sync(0xffffffffu, mx2, 2));
        float mn1 = fmaxf(m1, mx1), mn2 = fmaxf(m2, mx2);

        float sum1 = 0.f, sum2 = 0.f;
        uint32_t plo[8], phi[8];
#pragma unroll
        for (int n = 0; n < 8; n++) {
            float p0 = __expf(sacc[n][0] - mn1);
            float p1 = __expf(sacc[n][1] - mn1);
            float p2 = __expf(sacc[n][2] - mn2);
            float p3 = __expf(sacc[n][3] - mn2);
            __half2 hl = __floats2half2_rn(p0, p1);
            __half2 hh = __floats2half2_rn(p2, p3);
            plo[n] = h2_u32(hl);
            phi[n] = h2_u32(hh);
            float2 fl = __half22float2(hl);
            float2 fh = __half22float2(hh);
            sum1 += fl.x + fl.y;
            sum2 += fh.x + fh.y;
        }
        sum1 += __shfl_xor_sync(0xffffffffu, sum1, 1);
        sum1 += __shfl_xor_sync(0xffffffffu, sum1, 2);
        sum2 += __shfl_xor_sync(0xffffffffu, sum2, 1);
        sum2 += __shfl_xor_sync(0xffffffffu, sum2, 2);

        float sc1 = __expf(m1 - mn1), sc2 = __expf(m2 - mn2);
        l1 = l1 * sc1 + sum1;
        l2 = l2 * sc2 + sum2;
        m1 = mn1; m2 = mn2;
#pragma unroll
        for (int n = 0; n < 8; n++) {
            oacc[n][0] *= sc1; oacc[n][1] *= sc1;
            oacc[n][2] *= sc2; oacc[n][3] *= sc2;
        }

        // ---- O += P V  (this warp's 64 HD cols only) ----
#pragma unroll
        for (int sk = 0; sk < 4; sk++) {
            uint32_t a0 = plo[2 * sk], a1 = phi[2 * sk];
            uint32_t a2 = plo[2 * sk + 1], a3 = phi[2 * sk + 1];
#pragma unroll
            for (int j2 = 0; j2 < 4; j2++) {
                uint32_t bb[4];
                ldsm_x4_t(bb, Vb + v_off + (uint32_t)(sk * 16 * KROWH * 2 + j2 * 32));
                mma_f16(oacc[2 * j2],     a0, a1, a2, a3, bb[0], bb[1]);
                mma_f16(oacc[2 * j2 + 1], a0, a1, a2, a3, bb[2], bb[3]);
            }
        }
        __syncthreads();
    }

    // ---- write y (this warp's 64 HD cols) ----
    float inv1 = 1.0f / l1, inv2 = 1.0f / l2;
    __half* y1 = g_y + ((size_t)b * T_ + qrow1) * D_ + h * HD_ + half * 64;
    __half* y2 = g_y + ((size_t)b * T_ + qrow2) * D_ + h * HD_ + half * 64;
#pragma unroll
    for (int n = 0; n < 8; n++) {
        int col = 8 * n + 2 * cc;
        *(__half2*)(y1 + col) = __floats2half2_rn(oacc[n][0] * inv1, oacc[n][1] * inv1);
        *(__half2*)(y2 + col) = __floats2half2_rn(oacc[n][2] * inv2, oacc[n][3] * inv2);
    }
}

// ============================================================================
extern "C" void kernel_launch(void* const* d_in, const int* in_sizes, int n_in,
                              void* d_out, int out_size)
{
    const float* x     = (const float*)d_in[0];
    const float* w_qkv = (const float*)d_in[1];
    const float* w_out = (const float*)d_in[2];
    float* out = (float*)d_out;

    cudaFuncSetAttribute(attn_kernel, cudaFuncAttributeMaxDynamicSharedMemorySize,
                         ATTN_SMEM_BYTES);
    cudaFuncSetAttribute(gemm_qkv_kernel, cudaFuncAttributeMaxDynamicSharedMemorySize,
                         GEMM_SMEM_BYTES);
    cudaFuncSetAttribute(gemm_out_kernel, cudaFuncAttributeMaxDynamicSharedMemorySize,
                         GEMM_SMEM_BYTES);

    rope_tab_kernel<<<(T_ * 64 + 255) / 256, 256>>>();
    int total4 = NX4 + NWQ4 + NWO4;
    conv_all_kernel<<<(total4 + 255) / 256, 256>>>((const float4*)x,
                                                   (const float4*)w_qkv,
                                                   (const float4*)w_out);

    dim3 g1(6144 / 128, (B_ * T_) / 128);
    gemm_qkv_kernel<<<g1, 256, GEMM_SMEM_BYTES>>>();

    dim3 g2(T_ / 128, H_, B_);
    attn_kernel<<<g2, ATHREADS, ATTN_SMEM_BYTES>>>();

    dim3 g3(D_ / 128, (B_ * T_) / 128);
    gemm_out_kernel<<<g3, 256, GEMM_SMEM_BYTES>>>(out);
}

// round 17
// speedup vs baseline: 1.1264x; 1.1264x over previous
#include <cuda_runtime.h>
#include <cuda_fp16.h>
#include <math.h>
#include <stdint.h>

// Problem constants
#define B_  2
#define T_  2048
#define D_  2048
#define H_  16
#define HD_ 128

// ---------------- scratch (static device globals; no allocation) -------------
__device__ __align__(16) __half g_q[(size_t)B_ * H_ * T_ * HD_];   // rope applied
__device__ __align__(16) __half g_k[(size_t)B_ * H_ * T_ * HD_];
__device__ __align__(16) __half g_v[(size_t)B_ * H_ * T_ * HD_];
__device__ __align__(16) __half g_y[(size_t)B_ * T_ * D_];         // attn output
__device__ __align__(16) __half g_xh[(size_t)B_ * T_ * D_];        // x fp16
__device__ __align__(16) __half g_wqh[(size_t)D_ * 3 * HD_ * H_];  // w_qkv fp16
__device__ __align__(16) __half g_woh[(size_t)D_ * D_];            // w_out fp16
__device__ float2 g_rope_tab[T_ * 64];                             // (cos, sin)

// element counts (float4 granules)
#define NX4  (B_ * T_ * D_ / 4)
#define NWQ4 (D_ * 3 * HD_ * H_ / 4)
#define NWO4 (D_ * D_ / 4)

// ============================================================================
// helpers
// ============================================================================
__device__ __forceinline__ uint32_t h2_u32(__half2 h) {
    return *reinterpret_cast<uint32_t*>(&h);
}

__device__ __forceinline__ void mma_f16(float c[4],
                                        uint32_t a0, uint32_t a1, uint32_t a2, uint32_t a3,
                                        uint32_t b0, uint32_t b1) {
    asm volatile(
        "mma.sync.aligned.m16n8k16.row.col.f32.f16.f16.f32 "
        "{%0,%1,%2,%3}, {%4,%5,%6,%7}, {%8,%9}, {%0,%1,%2,%3};"
        : "+f"(c[0]), "+f"(c[1]), "+f"(c[2]), "+f"(c[3])
        : "r"(a0), "r"(a1), "r"(a2), "r"(a3), "r"(b0), "r"(b1));
}

__device__ __forceinline__ void ldsm_x4(uint32_t r[4], uint32_t addr) {
    asm volatile("ldmatrix.sync.aligned.m8n8.x4.shared.b16 {%0,%1,%2,%3}, [%4];"
                 : "=r"(r[0]), "=r"(r[1]), "=r"(r[2]), "=r"(r[3]) : "r"(addr));
}
__device__ __forceinline__ void ldsm_x4_t(uint32_t r[4], uint32_t addr) {
    asm volatile("ldmatrix.sync.aligned.m8n8.x4.trans.shared.b16 {%0,%1,%2,%3}, [%4];"
                 : "=r"(r[0]), "=r"(r[1]), "=r"(r[2]), "=r"(r[3]) : "r"(addr));
}

__device__ __forceinline__ void cpa16s(uint32_t saddr, const void* src) {
    asm volatile("cp.async.cg.shared.global [%0], [%1], 16;" :: "r"(saddr), "l"(src));
}
__device__ __forceinline__ void cpa_commit() { asm volatile("cp.async.commit_group;"); }
template<int N> __device__ __forceinline__ void cpa_wait() {
    asm volatile("cp.async.wait_group %0;" :: "n"(N));
}

__device__ __forceinline__ uint32_t smem_u32(const void* p) {
    uint32_t a;
    asm("{ .reg .u64 t; cvta.to.shared.u64 t, %1; cvt.u32.u64 %0, t; }" : "=r"(a) : "l"(p));
    return a;
}

// ============================================================================
// prep kernels
// ============================================================================
__global__ void rope_tab_kernel()
{
    int idx = blockIdx.x * blockDim.x + threadIdx.x;
    if (idx >= T_ * 64) return;
    int t = idx >> 6, i = idx & 63;
    float inv = powf(10000.0f, -((float)(2 * i)) * (1.0f / 128.0f));
    float ang = (float)t * inv;
    float s, c;
    sincosf(ang, &s, &c);
    g_rope_tab[idx] = make_float2(c, s);
}

__device__ __forceinline__ uint2 f4_to_h4(float4 v) {
    return make_uint2(h2_u32(__floats2half2_rn(v.x, v.y)),
                      h2_u32(__floats2half2_rn(v.z, v.w)));
}

__global__ void conv_all_kernel(const float4* __restrict__ x,
                                const float4* __restrict__ wq,
                                const float4* __restrict__ wo)
{
    int i = blockIdx.x * blockDim.x + threadIdx.x;
    if (i < NX4) {
        ((uint2*)g_xh)[i] = f4_to_h4(x[i]);
        return;
    }
    i -= NX4;
    if (i < NWQ4) {
        ((uint2*)g_wqh)[i] = f4_to_h4(wq[i]);
        return;
    }
    i -= NWQ4;
    if (i < NWO4) {
        ((uint2*)g_woh)[i] = f4_to_h4(wo[i]);
    }
}

// ============================================================================
// fp16 GEMM 128x128, k-chunk 64, 256 threads (8 warps 2m x 4n), occ 2.
// 3-stage cp.async pipeline, one __syncthreads per k-chunk. (round-13 body)
// ============================================================================
#define AROW 72
#define BROW 136
#define ABUF_BYTES (128 * AROW * 2)                 // 18432
#define BBUF_BYTES (64 * BROW * 2)                  // 17408
#define STAGE_BYTES (ABUF_BYTES + BBUF_BYTES)       // 35840
#define GEMM_SMEM_BYTES (3 * STAGE_BYTES)           // 107520

struct GemmCtx { int m0, n0, lane, warp_m, warp_n; };

template <typename Epi>
__device__ __forceinline__ void gemm_f16_cpa(const __half* __restrict__ A,
                                             const __half* __restrict__ Bg,
                                             int Kd, int Nd, Epi epi)
{
    extern __shared__ __half smg[];
    const uint32_t sb = smem_u32(smg);

    const int tid = threadIdx.x;
    const int lane = tid & 31;
    const int warp = tid >> 5;
    const int warp_m = warp & 1;
    const int warp_n = warp >> 1;
    const int m0 = blockIdx.y * 128;
    const int n0 = blockIdx.x * 128;

    float acc[4][4][4];
#pragma unroll
    for (int mt = 0; mt < 4; mt++)
#pragma unroll
        for (int nt = 0; nt < 4; nt++)
#pragma unroll
            for (int e = 0; e < 4; e++) acc[mt][nt][e] = 0.f;

    const uint32_t a_off =
        (uint32_t)((warp_m * 64 + (lane & 7) + ((lane >> 3) & 1) * 8) * AROW +
                   (lane >> 4) * 8) * 2;
    const uint32_t b_off = (uint32_t)ABUF_BYTES +
        (uint32_t)(((lane & 7) + ((lane >> 3) & 1) * 8) * BROW +
                   warp_n * 32 + (lane >> 4) * 8) * 2;

#define LOADG(it, stage)                                                          \
    {                                                                             \
        uint32_t ab = sb + (stage) * STAGE_BYTES;                                 \
        uint32_t bb = ab + ABUF_BYTES;                                            \
        int kk = (it) * 64;                                                       \
        _Pragma("unroll")                                                         \
        for (int i = 0; i < 4; i++) {                                             \
            int idx = tid + 256 * i;                                              \
            int row = idx >> 3, c = idx & 7;                                      \
            cpa16s(ab + (uint32_t)(row * (AROW * 2) + c * 16),                    \
                   A + (size_t)(m0 + row) * Kd + kk + c * 8);                     \
        }                                                                         \
        _Pragma("unroll")                                                         \
        for (int i = 0; i < 4; i++) {                                             \
            int idx = tid + 256 * i;                                              \
            int row = idx >> 4, c = idx & 15;                                     \
            cpa16s(bb + (uint32_t)(row * (BROW * 2) + c * 16),                    \
                   Bg + (size_t)(kk + row) * Nd + n0 + c * 8);                    \
        }                                                                         \
        cpa_commit();                                                             \
    }

    const int nt = Kd / 64;   // 32
    LOADG(0, 0);
    LOADG(1, 1);

    for (int it = 0; it < nt; it++) {
        if (it + 1 < nt) cpa_wait<1>(); else cpa_wait<0>();
        __syncthreads();

        if (it + 2 < nt) LOADG(it + 2, (it + 2) % 3);

        const uint32_t base = sb + (it % 3) * STAGE_BYTES;
#pragma unroll
        for (int s = 0; s < 4; s++) {
            uint32_t af[4][4];
#pragma unroll
            for (int mt = 0; mt < 4; mt++)
                ldsm_x4(af[mt], base + a_off + (uint32_t)(mt * 16 * AROW * 2 + s * 32));
            uint32_t bf[2][4];
#pragma unroll
            for (int nt2 = 0; nt2 < 2; nt2++)
                ldsm_x4_t(bf[nt2], base + b_off + (uint32_t)(s * 16 * BROW * 2 + nt2 * 32));
#pragma unroll
            for (int mt = 0; mt < 4; mt++)
#pragma unroll
                for (int ntv = 0; ntv < 4; ntv++)
                    mma_f16(acc[mt][ntv],
                            af[mt][0], af[mt][1], af[mt][2], af[mt][3],
                            bf[ntv >> 1][(ntv & 1) * 2], bf[ntv >> 1][(ntv & 1) * 2 + 1]);
        }
    }
#undef LOADG

    GemmCtx ctx{m0, n0, lane, warp_m, warp_n};
    epi(ctx, acc);
}

// ---------------- epilogues --------------------------------------------------
__device__ __forceinline__ void qkv_scatter_pair(int row, int col, float v0, float v1)
{
    int b = row >> 11, t = row & (T_ - 1);
    int h = col / (3 * HD_);
    int r = col % (3 * HD_);                 // always even
    size_t base = (((size_t)(b * H_ + h)) * T_ + t) * HD_;
    if (r < 2 * HD_) {
        __half* dst = (r < HD_) ? g_q : g_k;
        int rr = r & (HD_ - 1);
        float2 cs = g_rope_tab[(t << 6) + (rr >> 1)];
        float o0 = v0 * cs.x - v1 * cs.y;
        float o1 = v0 * cs.y + v1 * cs.x;
        *(__half2*)&dst[base + rr] = __floats2half2_rn(o0, o1);
    } else {
        *(__half2*)&g_v[base + r - 2 * HD_] = __floats2half2_rn(v0, v1);
    }
}

struct QkvEpi {
    __device__ __forceinline__ void operator()(const GemmCtx& c, float acc[4][4][4]) const {
#pragma unroll
        for (int mt = 0; mt < 4; mt++) {
            int row = c.m0 + c.warp_m * 64 + mt * 16 + (c.lane >> 2);
#pragma unroll
            for (int nt = 0; nt < 4; nt++) {
                int col = c.n0 + c.warp_n * 32 + nt * 8 + (c.lane & 3) * 2;
                qkv_scatter_pair(row,     col, acc[mt][nt][0], acc[mt][nt][1]);
                qkv_scatter_pair(row + 8, col, acc[mt][nt][2], acc[mt][nt][3]);
            }
        }
    }
};

struct OutEpi {
    float* C;
    __device__ __forceinline__ void operator()(const GemmCtx& c, float acc[4][4][4]) const {
#pragma unroll
        for (int mt = 0; mt < 4; mt++) {
            int row = c.m0 + c.warp_m * 64 + mt * 16 + (c.lane >> 2);
#pragma unroll
            for (int nt = 0; nt < 4; nt++) {
                int col = c.n0 + c.warp_n * 32 + nt * 8 + (c.lane & 3) * 2;
                *(float2*)(C + (size_t)row * D_ + col) =
                    make_float2(acc[mt][nt][0], acc[mt][nt][1]);
                *(float2*)(C + (size_t)(row + 8) * D_ + col) =
                    make_float2(acc[mt][nt][2], acc[mt][nt][3]);
            }
        }
    }
};

__global__ __launch_bounds__(256, 2) void gemm_qkv_kernel()
{
    gemm_f16_cpa(g_xh, g_wqh, D_, 3 * HD_ * H_, QkvEpi{});
}

__global__ __launch_bounds__(256, 2) void gemm_out_kernel(float* __restrict__ C)
{
    gemm_f16_cpa(g_y, g_woh, D_, D_, OutEpi{C});
}

// ============================================================================
// Flash attention, fp16 mma.m16n8k16, LPT order, occ 1 (round-15 body) with
// 128-row KV buffers: one barrier pair per 128 KV rows, two 64-row sub-steps.
// ============================================================================
#define KROWH 136
#define KV_TILE_BYTES (128 * KROWH * 2)           // 34816 (128 rows)
#define ATTN_SMEM_BYTES (4 * KV_TILE_BYTES)       // 139264

__device__ __forceinline__ void load_kv128(uint32_t sm_u, int buf,
                                           const __half* Kh, const __half* Vh,
                                           int k0, int tid)
{
    uint32_t kb = sm_u + buf * KV_TILE_BYTES;
    uint32_t vb = sm_u + 2 * KV_TILE_BYTES + buf * KV_TILE_BYTES;
#pragma unroll
    for (int i = 0; i < 8; i++) {
        int idx = tid + i * 256;
        int row = idx >> 4, c16 = idx & 15;
        cpa16s(kb + row * (KROWH * 2) + c16 * 16,
               Kh + (size_t)(k0 + row) * HD_ + c16 * 8);
    }
#pragma unroll
    for (int i = 0; i < 8; i++) {
        int idx = tid + i * 256;
        int row = idx >> 4, c16 = idx & 15;
        cpa16s(vb + row * (KROWH * 2) + c16 * 16,
               Vh + (size_t)(k0 + row) * HD_ + c16 * 8);
    }
    cpa_commit();
}

__global__ __launch_bounds__(256, 1) void attn_kernel()
{
    extern __shared__ __half smh[];
    const uint32_t sm_u = smem_u32(smh);

    const int b = blockIdx.z, h = blockIdx.y;
    const int q0 = ((int)gridDim.x - 1 - (int)blockIdx.x) * 128;  // longest first
    const __half* Qh = g_q + (((size_t)(b * H_ + h)) * T_) * HD_;
    const __half* Kh = g_k + (((size_t)(b * H_ + h)) * T_) * HD_;
    const __half* Vh = g_v + (((size_t)(b * H_ + h)) * T_) * HD_;

    const int tid = threadIdx.x;
    const int lane = tid & 31;
    const int w = tid >> 5;
    const int r1 = lane >> 2;
    const int cc = lane & 3;
    const int qrow1 = q0 + w * 16 + r1;
    const int qrow2 = qrow1 + 8;
    const int nbig = (q0 >> 7) + 1;     // 128-row KV tiles covering 0..q0+127

    load_kv128(sm_u, 0, Kh, Vh, 0, tid);

    uint32_t qf[8][4];
#pragma unroll
    for (int s = 0; s < 8; s++) {
        qf[s][0] = *(const uint32_t*)(Qh + (size_t)qrow1 * HD_ + 16 * s + 2 * cc);
        qf[s][1] = *(const uint32_t*)(Qh + (size_t)qrow2 * HD_ + 16 * s + 2 * cc);
        qf[s][2] = *(const uint32_t*)(Qh + (size_t)qrow1 * HD_ + 16 * s + 8 + 2 * cc);
        qf[s][3] = *(const uint32_t*)(Qh + (size_t)qrow2 * HD_ + 16 * s + 8 + 2 * cc);
    }

    float oacc[16][4];
#pragma unroll
    for (int n = 0; n < 16; n++)
#pragma unroll
        for (int e = 0; e < 4; e++) oacc[n][e] = 0.f;
    float m1 = -1e30f, m2 = -1e30f, l1 = 0.f, l2 = 0.f;
    const float sm_scale = 0.08838834764831845f;

    const uint32_t k_off =
        (uint32_t)(((lane & 7) + (lane >> 4) * 8) * KROWH + ((lane >> 3) & 1) * 8) * 2;
    const uint32_t v_off =
        (uint32_t)(((lane & 7) + ((lane >> 3) & 1) * 8) * KROWH + (lane >> 4) * 8) * 2;

    for (int t = 0; t < nbig; t++) {
        const uint32_t Kbase = sm_u + (t & 1) * KV_TILE_BYTES;
        const uint32_t Vbase = sm_u + 2 * KV_TILE_BYTES + (t & 1) * KV_TILE_BYTES;

        if (t + 1 < nbig) {
            load_kv128(sm_u, (t + 1) & 1, Kh, Vh, (t + 1) * 128, tid);
            cpa_wait<1>();
        } else {
            cpa_wait<0>();
        }
        __syncthreads();

        const bool need_mask = (t == nbig - 1);

#pragma unroll
        for (int u = 0; u < 2; u++) {
            const int k0 = t * 128 + u * 64;
            const uint32_t Kb = Kbase + (uint32_t)(u * 64 * KROWH * 2);
            const uint32_t Vb = Vbase + (uint32_t)(u * 64 * KROWH * 2);

            float sacc[8][4];
#pragma unroll
            for (int n = 0; n < 8; n++)
#pragma unroll
                for (int e = 0; e < 4; e++) sacc[n][e] = 0.f;

#pragma unroll
            for (int s = 0; s < 8; s++) {
#pragma unroll
                for (int j = 0; j < 4; j++) {
                    uint32_t bb[4];
                    ldsm_x4(bb, Kb + k_off + (uint32_t)(j * 16 * KROWH * 2 + s * 32));
                    mma_f16(sacc[2 * j],     qf[s][0], qf[s][1], qf[s][2], qf[s][3], bb[0], bb[1]);
                    mma_f16(sacc[2 * j + 1], qf[s][0], qf[s][1], qf[s][2], qf[s][3], bb[2], bb[3]);
                }
            }

            float mx1 = -1e30f, mx2 = -1e30f;
#pragma unroll
            for (int n = 0; n < 8; n++) {
                int col = k0 + 8 * n + 2 * cc;
                float s0 = sacc[n][0] * sm_scale;
                float s1 = sacc[n][1] * sm_scale;
                float s2 = sacc[n][2] * sm_scale;
                float s3 = sacc[n][3] * sm_scale;
                if (need_mask) {
                    if (col     > qrow1) s0 = -1e30f;
                    if (col + 1 > qrow1) s1 = -1e30f;
                    if (col     > qrow2) s2 = -1e30f;
                    if (col + 1 > qrow2) s3 = -1e30f;
                }
                sacc[n][0] = s0; sacc[n][1] = s1; sacc[n][2] = s2; sacc[n][3] = s3;
                mx1 = fmaxf(mx1, fmaxf(s0, s1));
                mx2 = fmaxf(mx2, fmaxf(s2, s3));
            }
            mx1 = fmaxf(mx1, __shfl_xor_sync(0xffffffffu, mx1, 1));
            mx1 = fmaxf(mx1, __shfl_xor_sync(0xffffffffu, mx1, 2));
            mx2 = fmaxf(mx2, __shfl_xor_sync(0xffffffffu, mx2, 1));
            mx2 = fmaxf(mx2, __shfl_xor_sync(0xffffffffu, mx2, 2));
            float mn1 = fmaxf(m1, mx1), mn2 = fmaxf(m2, mx2);

            float sum1 = 0.f, sum2 = 0.f;
            uint32_t plo[8], phi[8];
#pragma unroll
            for (int n = 0; n < 8; n++) {
                float p0 = __expf(sacc[n][0] - mn1);
                float p1 = __expf(sacc[n][1] - mn1);
                float p2 = __expf(sacc[n][2] - mn2);
                float p3 = __expf(sacc[n][3] - mn2);
                __half2 hl = __floats2half2_rn(p0, p1);
                __half2 hh = __floats2half2_rn(p2, p3);
                plo[n] = h2_u32(hl);
                phi[n] = h2_u32(hh);
                float2 fl = __half22float2(hl);
                float2 fh = __half22float2(hh);
                sum1 += fl.x + fl.y;
                sum2 += fh.x + fh.y;
            }
            sum1 += __shfl_xor_sync(0xffffffffu, sum1, 1);
            sum1 += __shfl_xor_sync(0xffffffffu, sum1, 2);
            sum2 += __shfl_xor_sync(0xffffffffu, sum2, 1);
            sum2 += __shfl_xor_sync(0xffffffffu, sum2, 2);

            float sc1 = __expf(m1 - mn1), sc2 = __expf(m2 - mn2);
            l1 = l1 * sc1 + sum1;
            l2 = l2 * sc2 + sum2;
            m1 = mn1; m2 = mn2;
#pragma unroll
            for (int n = 0; n < 16; n++) {
                oacc[n][0] *= sc1; oacc[n][1] *= sc1;
                oacc[n][2] *= sc2; oacc[n][3] *= sc2;
            }

#pragma unroll
            for (int sk = 0; sk < 4; sk++) {
                uint32_t a0 = plo[2 * sk], a1 = phi[2 * sk];
                uint32_t a2 = plo[2 * sk + 1], a3 = phi[2 * sk + 1];
#pragma unroll
                for (int j2 = 0; j2 < 8; j2++) {
                    uint32_t bb[4];
                    ldsm_x4_t(bb, Vb + v_off + (uint32_t)(sk * 16 * KROWH * 2 + j2 * 32));
                    mma_f16(oacc[2 * j2],     a0, a1, a2, a3, bb[0], bb[1]);
                    mma_f16(oacc[2 * j2 + 1], a0, a1, a2, a3, bb[2], bb[3]);
                }
            }
        }
        __syncthreads();
    }

    float inv1 = 1.0f / l1, inv2 = 1.0f / l2;
    __half* y1 = g_y + ((size_t)b * T_ + qrow1) * D_ + h * HD_;
    __half* y2 = g_y + ((size_t)b * T_ + qrow2) * D_ + h * HD_;
#pragma unroll
    for (int n = 0; n < 16; n++) {
        int col = 8 * n + 2 * cc;
        *(__half2*)(y1 + col) = __floats2half2_rn(oacc[n][0] * inv1, oacc[n][1] * inv1);
        *(__half2*)(y2 + col) = __floats2half2_rn(oacc[n][2] * inv2, oacc[n][3] * inv2);
    }
}

// ============================================================================
extern "C" void kernel_launch(void* const* d_in, const int* in_sizes, int n_in,
                              void* d_out, int out_size)
{
    const float* x     = (const float*)d_in[0];
    const float* w_qkv = (const float*)d_in[1];
    const float* w_out = (const float*)d_in[2];
    float* out = (float*)d_out;

    cudaFuncSetAttribute(attn_kernel, cudaFuncAttributeMaxDynamicSharedMemorySize,
                         ATTN_SMEM_BYTES);
    cudaFuncSetAttribute(gemm_qkv_kernel, cudaFuncAttributeMaxDynamicSharedMemorySize,
                         GEMM_SMEM_BYTES);
    cudaFuncSetAttribute(gemm_out_kernel, cudaFuncAttributeMaxDynamicSharedMemorySize,
                         GEMM_SMEM_BYTES);

    rope_tab_kernel<<<(T_ * 64 + 255) / 256, 256>>>();
    int total4 = NX4 + NWQ4 + NWO4;
    conv_all_kernel<<<(total4 + 255) / 256, 256>>>((const float4*)x,
                                                   (const float4*)w_qkv,
                                                   (const float4*)w_out);

    dim3 g1(6144 / 128, (B_ * T_) / 128);
    gemm_qkv_kernel<<<g1, 256, GEMM_SMEM_BYTES>>>();

    dim3 g2(T_ / 128, H_, B_);
    attn_kernel<<<g2, 256, ATTN_SMEM_BYTES>>>();

    dim3 g3(D_ / 128, (B_ * T_) / 128);
    gemm_out_kernel<<<g3, 256, GEMM_SMEM_BYTES>>>(out);
}